// round 4
// baseline (speedup 1.0000x reference)
#include <cuda_runtime.h>
#include <math.h>

#define BB   256     // batch
#define DM   512     // d_model
#define NV   1376    // n_vars
#define Gm   32      // batch rows per block in embed kernel
#define MAXS 128     // max slots supported (actual S = 96)

// ---------------- device-global scratch (no allocations allowed) ----------------
__device__ int g_S, g_total;
__device__ int g_c[MAXS], g_L[MAXS], g_P[MAXS], g_k[MAXS], g_off[MAXS];
__device__ float g_pe[MAXS * DM];
__device__ unsigned char g_maskrow[NV];

// ---------------- setup: block 0 = plan, blocks 1..MAXS = positional emb -------
__global__ void setup_kernel(const int* __restrict__ seg) {
    if (blockIdx.x == 0) {
        __shared__ int sFirstNeg, sS;
        int tid = threadIdx.x;
        if (tid == 0) { sFirstNeg = NV; sS = 0; }
        __syncthreads();
        // first -1 breaks validity (input has none, but honor the semantics)
        for (int t = tid; t < NV; t += blockDim.x)
            if (seg[t] < 0) atomicMin(&sFirstNeg, t);
        __syncthreads();
        int validN = sFirstNeg;
        // segment starts; consecutive ids => id is the slot index
        for (int t = tid; t < validN; t += blockDim.x) {
            int v = seg[t];
            int prev = (t == 0) ? -2 : seg[t - 1];
            if (v != prev) g_c[v] = t;
            atomicMax(&sS, v + 1);
        }
        __syncthreads();
        int S = sS;
        const int PL[4] = {5, 10, 17, 24};
        for (int s = tid; s < S; s += blockDim.x) {
            int cs = g_c[s];
            int L = ((s + 1 < S) ? g_c[s + 1] : validN) - cs;
            int bestk = 0, bd = abs(L - PL[0]);
#pragma unroll
            for (int k = 1; k < 4; k++) {
                int dd = abs(L - PL[k]);
                if (dd < bd) { bd = dd; bestk = k; }   // strict < keeps first on tie (argmin)
            }
            g_L[s] = L; g_k[s] = bestk; g_P[s] = PL[bestk];
        }
        __syncthreads();
        if (tid == 0) {
            int acc = 0;
            for (int s = 0; s < S; s++) { g_off[s] = acc; acc += g_P[s]; }
            g_total = acc;
            g_S = S;
        }
        __syncthreads();
        // one mask row pattern (identical for every batch row)
        for (int s = tid; s < S; s += blockDim.x) {
            int off = g_off[s], L = g_L[s], P = g_P[s];
            for (int t = 0; t < P; t++)
                g_maskrow[off + t] = (t >= L) ? 1 : 0;
        }
    } else {
        // sin/cos positional embedding table: pe[s, 2j] = sin(s*f_j), pe[s, 2j+1] = cos
        int s = blockIdx.x - 1;
        int j = threadIdx.x;                       // 0..255
        float freq = expf(-(float)(2 * j) * (logf(10000.0f) / (float)DM));
        float sv, cv;
        sincosf((float)s * freq, &sv, &cv);
        g_pe[s * DM + 2 * j]     = sv;
        g_pe[s * DM + 2 * j + 1] = cv;
    }
}

// ---------------- main embedding -----------------------------------------------
// One block handles (slot s, 32 batch rows). 256 threads, each owns 2 output
// channels d = 2*tid, d+1. W rows held in registers (packed f32x2 pairs along t),
// patch values staged in shared and reused across all 32 batch rows.
template <int P>
__device__ __forceinline__ void run_patch(
    const float* __restrict__ x, const float* __restrict__ Wk,
    float* __restrict__ out, float (*sv)[32],
    int s, int b0, int c, int L, int S)
{
    constexpr int PP = P + (P & 1);   // pad odd P with a zero slot
    constexpr int NP = PP / 2;        // f32x2 pairs along t
    int tid = threadIdx.x;

    // stage patch values (with zero padding) for Gm batch rows
    for (int i = tid; i < Gm * PP; i += 256) {
        int g = i / PP, t = i - g * PP;
        float val = 0.0f;
        if (t < P && t < L) val = x[(size_t)(b0 + g) * NV + c + t];
        sv[g][t] = val;
    }

    int d = tid << 1;   // even -> 8B-aligned f2 loads/stores
    float wa[PP], wb[PP];
    const float* rA = Wk + (size_t)d * P;
    const float* rB = rA + P;
#pragma unroll
    for (int j = 0; j < P / 2; j++) {          // rA always 8B-aligned (d even)
        float2 p = *(const float2*)(rA + 2 * j);
        wa[2 * j] = p.x; wa[2 * j + 1] = p.y;
    }
    if (P & 1) { wa[P - 1] = rA[P - 1]; wa[P] = 0.0f; }
    if constexpr ((P & 1) == 0) {
#pragma unroll
        for (int j = 0; j < P / 2; j++) {
            float2 p = *(const float2*)(rB + 2 * j);
            wb[2 * j] = p.x; wb[2 * j + 1] = p.y;
        }
    } else {
        wb[0] = rB[0];                         // rB+1 is 8B-aligned for odd P
#pragma unroll
        for (int j = 0; j < (P - 1) / 2; j++) {
            float2 p = *(const float2*)(rB + 1 + 2 * j);
            wb[1 + 2 * j] = p.x; wb[2 + 2 * j] = p.y;
        }
        wb[P] = 0.0f;
    }

    unsigned long long wa2[NP], wb2[NP];
#pragma unroll
    for (int j = 0; j < NP; j++) {
        asm("mov.b64 %0, {%1, %2};" : "=l"(wa2[j]) : "f"(wa[2 * j]), "f"(wa[2 * j + 1]));
        asm("mov.b64 %0, {%1, %2};" : "=l"(wb2[j]) : "f"(wb[2 * j]), "f"(wb[2 * j + 1]));
    }
    float2 pe2 = *(const float2*)(g_pe + s * DM + d);

    __syncthreads();

#pragma unroll
    for (int g = 0; g < Gm; g++) {
        unsigned long long accA = 0ull, accB = 0ull;   // bit pattern of (0.f, 0.f)
#pragma unroll
        for (int j = 0; j < NP; j++) {
            float2 vp = *(const float2*)(&sv[g][2 * j]);
            unsigned long long v2;
            asm("mov.b64 %0, {%1, %2};" : "=l"(v2) : "f"(vp.x), "f"(vp.y));
            asm("fma.rn.f32x2 %0, %1, %2, %0;" : "+l"(accA) : "l"(v2), "l"(wa2[j]));
            asm("fma.rn.f32x2 %0, %1, %2, %0;" : "+l"(accB) : "l"(v2), "l"(wb2[j]));
        }
        float a0, a1, c0, c1;
        asm("mov.b64 {%0, %1}, %2;" : "=f"(a0), "=f"(a1) : "l"(accA));
        asm("mov.b64 {%0, %1}, %2;" : "=f"(c0), "=f"(c1) : "l"(accB));
        float2 o;
        o.x = a0 + a1 + pe2.x;
        o.y = c0 + c1 + pe2.y;
        *(float2*)(out + ((size_t)(b0 + g) * S + s) * DM + d) = o;
    }
}

__global__ void __launch_bounds__(256) embed_kernel(
    const float* __restrict__ x,
    const float* __restrict__ W0, const float* __restrict__ W1,
    const float* __restrict__ W2, const float* __restrict__ W3,
    float* __restrict__ out, int with_mask)
{
    __shared__ __align__(16) float sv[Gm][32];
    int s = blockIdx.y;
    int S = g_S;
    if (s >= S) {
        // repurpose out-of-range blocks to broadcast the mask rows
        if (!with_mask) return;
        int ds = s - S;
        if (ds >= 32) return;
        int b = ds * gridDim.x + blockIdx.x;     // gridDim.x = 8 -> covers 256 rows
        if (b >= BB) return;
        int total = g_total;
        float* m = out + (size_t)BB * S * DM + (size_t)b * total;
        for (int i = threadIdx.x; i < total; i += blockDim.x)
            m[i] = g_maskrow[i] ? 1.0f : 0.0f;
        return;
    }
    int b0 = blockIdx.x * Gm;
    int c = g_c[s], L = g_L[s], k = g_k[s];
    switch (k) {
        case 0:  run_patch<5 >(x, W0, out, sv, s, b0, c, L, S); break;
        case 1:  run_patch<10>(x, W1, out, sv, s, b0, c, L, S); break;
        case 2:  run_patch<17>(x, W2, out, sv, s, b0, c, L, S); break;
        default: run_patch<24>(x, W3, out, sv, s, b0, c, L, S); break;
    }
}

// ---------------- launch --------------------------------------------------------
extern "C" void kernel_launch(void* const* d_in, const int* in_sizes, int n_in,
                              void* d_out, int out_size) {
    const float* x   = (const float*)d_in[0];
    const int*   seg = (const int*)  d_in[1];
    const float* W0  = (const float*)d_in[2];
    const float* W1  = (const float*)d_in[3];
    const float* W2  = (const float*)d_in[4];
    const float* W3  = (const float*)d_in[5];
    float* out = (float*)d_out;

    // If the harness concatenates (out, mask) the total is not a multiple of B*D.
    int with_mask = (out_size % (BB * DM)) != 0;

    setup_kernel<<<MAXS + 1, 256>>>(seg);
    dim3 grid(BB / Gm, MAXS);
    embed_kernel<<<grid, 256>>>(x, W0, W1, W2, W3, out, with_mask);
    (void)in_sizes; (void)n_in;
}